// round 1
// baseline (speedup 1.0000x reference)
#include <cuda_runtime.h>
#include <math.h>

// ---------------------------------------------------------------------------
// Fused transformer block: B=2048, N=15, C=1024, H=16, HS=64
// Pipeline:
//  1. xj = LN(joint, g1,b1); xi = LN(relation, g2,b2)
//  2. Jqkv = xj @ W_Jqkv   [30720,3072]   (tf32 mma GEMM)
//  3. Iqkv = xi @ W_Iqk    [30720,3072]
//  4. attention per (b,h): softmax((JqJk^T + IqIk^T + Iv@Wc) * 0.125) @ Jv
//  5. joint = joint_feature + (attn @ W_proj + b_proj)
//  6. y = LN(joint); h = gelu(y@W_fc1+b1); out = joint + h@W_fc2+b2
// ---------------------------------------------------------------------------

#define M_ROWS 30720

// scratch (device globals: allocation-free per harness rules)
__device__ float g_bufA[(size_t)M_ROWS * 1024];   // xj, later ln(joint)
__device__ float g_bufB[(size_t)M_ROWS * 1024];   // xi, later attn output
__device__ float g_Jqkv[(size_t)M_ROWS * 3072];
__device__ float g_Iqkv[(size_t)M_ROWS * 3072];
__device__ float g_joint[(size_t)M_ROWS * 1024];
__device__ float g_hid[(size_t)M_ROWS * 512];

// ---------------------------------------------------------------------------
// LayerNorm: one block per row of 1024, 256 threads, float4 per thread
// ---------------------------------------------------------------------------
__global__ __launch_bounds__(256) void ln_kernel(
    const float* __restrict__ x, const float* __restrict__ g,
    const float* __restrict__ b, float* __restrict__ out) {
    int row = blockIdx.x;
    const float4* xr = reinterpret_cast<const float4*>(x + (size_t)row * 1024);
    float4 v = xr[threadIdx.x];
    float s = v.x + v.y + v.z + v.w;
    float sq = v.x * v.x + v.y * v.y + v.z * v.z + v.w * v.w;
#pragma unroll
    for (int o = 16; o > 0; o >>= 1) {
        s += __shfl_xor_sync(0xffffffffu, s, o);
        sq += __shfl_xor_sync(0xffffffffu, sq, o);
    }
    __shared__ float ss[8], ssq[8];
    int w = threadIdx.x >> 5;
    if ((threadIdx.x & 31) == 0) { ss[w] = s; ssq[w] = sq; }
    __syncthreads();
    float ts = 0.f, tq = 0.f;
#pragma unroll
    for (int i = 0; i < 8; i++) { ts += ss[i]; tq += ssq[i]; }
    float mean = ts * (1.0f / 1024.0f);
    float var = tq * (1.0f / 1024.0f) - mean * mean;
    float rstd = rsqrtf(var + 1e-5f);
    int c = threadIdx.x * 4;
    float4 gg = *reinterpret_cast<const float4*>(g + c);
    float4 bb = *reinterpret_cast<const float4*>(b + c);
    float4 o;
    o.x = (v.x - mean) * rstd * gg.x + bb.x;
    o.y = (v.y - mean) * rstd * gg.y + bb.y;
    o.z = (v.z - mean) * rstd * gg.z + bb.z;
    o.w = (v.w - mean) * rstd * gg.w + bb.w;
    reinterpret_cast<float4*>(out + (size_t)row * 1024)[threadIdx.x] = o;
}

// ---------------------------------------------------------------------------
// tf32 mma.sync GEMM: C[M,N] = A[M,K] @ B[K,N] (+ epilogue)
// Block tile 128x128x16, 8 warps, each warp 64x32 via m16n8k8 tf32 MMA.
// EPI: 0=none, 1=+bias+residual, 2=+bias then exact GELU
// ---------------------------------------------------------------------------
__device__ __forceinline__ float tf32r(float f) {
    unsigned u;
    asm("cvt.rna.tf32.f32 %0, %1;" : "=r"(u) : "f"(f));
    return __uint_as_float(u);
}

__device__ __forceinline__ float gelu_exact(float x) {
    return 0.5f * x * (1.0f + erff(x * 0.70710678118654752f));
}

template <int EPI>
__global__ __launch_bounds__(256) void gemm_tf32(
    const float* __restrict__ A, const float* __restrict__ B,
    const float* __restrict__ bias, const float* __restrict__ res,
    float* __restrict__ Cout, int M, int N, int K) {
    __shared__ float As[128][20];   // padded: A-frag LDS conflict-free
    __shared__ float Bs[16][136];   // padded: B-frag LDS conflict-free

    int tid = threadIdx.x;
    int bm = blockIdx.y * 128;
    int bn = blockIdx.x * 128;

    // global load mapping
    int a_m = tid >> 2;            // 0..63 (also +64)
    int a_k = (tid & 3) * 4;       // 0,4,8,12
    int b_k = tid >> 5;            // 0..7 (also +8)
    int b_n = (tid & 31) * 4;      // 0..124

    const float* Aptr = A + (size_t)(bm + a_m) * K + a_k;
    const float* Bptr = B + (size_t)b_k * N + bn + b_n;

    int lane = tid & 31, wid = tid >> 5;
    int wm = (wid >> 2) * 64;      // 0 / 64
    int wn = (wid & 3) * 32;       // 0..96
    int g = lane >> 2, tg = lane & 3;

    float acc[4][4][4];
#pragma unroll
    for (int a = 0; a < 4; a++)
#pragma unroll
        for (int b2 = 0; b2 < 4; b2++)
#pragma unroll
            for (int c = 0; c < 4; c++) acc[a][b2][c] = 0.f;

    float4 ra0 = *reinterpret_cast<const float4*>(Aptr);
    float4 ra1 = *reinterpret_cast<const float4*>(Aptr + (size_t)64 * K);
    float4 rb0 = *reinterpret_cast<const float4*>(Bptr);
    float4 rb1 = *reinterpret_cast<const float4*>(Bptr + (size_t)8 * N);

    *reinterpret_cast<float4*>(&As[a_m][a_k]) =
        make_float4(tf32r(ra0.x), tf32r(ra0.y), tf32r(ra0.z), tf32r(ra0.w));
    *reinterpret_cast<float4*>(&As[a_m + 64][a_k]) =
        make_float4(tf32r(ra1.x), tf32r(ra1.y), tf32r(ra1.z), tf32r(ra1.w));
    *reinterpret_cast<float4*>(&Bs[b_k][b_n]) =
        make_float4(tf32r(rb0.x), tf32r(rb0.y), tf32r(rb0.z), tf32r(rb0.w));
    *reinterpret_cast<float4*>(&Bs[b_k + 8][b_n]) =
        make_float4(tf32r(rb1.x), tf32r(rb1.y), tf32r(rb1.z), tf32r(rb1.w));
    __syncthreads();

    int nk = K >> 4;
    for (int t = 0; t < nk; ++t) {
        float4 na0, na1, nb0, nb1;
        if (t + 1 < nk) {
            const float* Ap = Aptr + (t + 1) * 16;
            na0 = *reinterpret_cast<const float4*>(Ap);
            na1 = *reinterpret_cast<const float4*>(Ap + (size_t)64 * K);
            const float* Bp = Bptr + (size_t)(t + 1) * 16 * N;
            nb0 = *reinterpret_cast<const float4*>(Bp);
            nb1 = *reinterpret_cast<const float4*>(Bp + (size_t)8 * N);
        }
#pragma unroll
        for (int kk = 0; kk < 16; kk += 8) {
            unsigned af[4][4], bf[4][2];
#pragma unroll
            for (int mt = 0; mt < 4; mt++) {
                int r = wm + mt * 16 + g;
                af[mt][0] = __float_as_uint(As[r][kk + tg]);
                af[mt][1] = __float_as_uint(As[r + 8][kk + tg]);
                af[mt][2] = __float_as_uint(As[r][kk + tg + 4]);
                af[mt][3] = __float_as_uint(As[r + 8][kk + tg + 4]);
            }
#pragma unroll
            for (int nt = 0; nt < 4; nt++) {
                int cN = wn + nt * 8 + g;
                bf[nt][0] = __float_as_uint(Bs[kk + tg][cN]);
                bf[nt][1] = __float_as_uint(Bs[kk + tg + 4][cN]);
            }
#pragma unroll
            for (int mt = 0; mt < 4; mt++)
#pragma unroll
                for (int nt = 0; nt < 4; nt++) {
                    asm volatile(
                        "mma.sync.aligned.m16n8k8.row.col.f32.tf32.tf32.f32 "
                        "{%0,%1,%2,%3},{%4,%5,%6,%7},{%8,%9},{%0,%1,%2,%3};"
                        : "+f"(acc[mt][nt][0]), "+f"(acc[mt][nt][1]),
                          "+f"(acc[mt][nt][2]), "+f"(acc[mt][nt][3])
                        : "r"(af[mt][0]), "r"(af[mt][1]), "r"(af[mt][2]),
                          "r"(af[mt][3]), "r"(bf[nt][0]), "r"(bf[nt][1]));
                }
        }
        if (t + 1 < nk) {
            __syncthreads();
            *reinterpret_cast<float4*>(&As[a_m][a_k]) =
                make_float4(tf32r(na0.x), tf32r(na0.y), tf32r(na0.z), tf32r(na0.w));
            *reinterpret_cast<float4*>(&As[a_m + 64][a_k]) =
                make_float4(tf32r(na1.x), tf32r(na1.y), tf32r(na1.z), tf32r(na1.w));
            *reinterpret_cast<float4*>(&Bs[b_k][b_n]) =
                make_float4(tf32r(nb0.x), tf32r(nb0.y), tf32r(nb0.z), tf32r(nb0.w));
            *reinterpret_cast<float4*>(&Bs[b_k + 8][b_n]) =
                make_float4(tf32r(nb1.x), tf32r(nb1.y), tf32r(nb1.z), tf32r(nb1.w));
            __syncthreads();
        }
    }

    // epilogue
#pragma unroll
    for (int mt = 0; mt < 4; mt++) {
        int row = bm + wm + mt * 16 + g;
#pragma unroll
        for (int nt = 0; nt < 4; nt++) {
            int col = bn + wn + nt * 8 + 2 * tg;
            size_t i0 = (size_t)row * N + col;
            size_t i1 = i0 + (size_t)8 * N;
            float c0 = acc[mt][nt][0], c1 = acc[mt][nt][1];
            float c2 = acc[mt][nt][2], c3 = acc[mt][nt][3];
            if (EPI == 1) {
                float2 bb = *reinterpret_cast<const float2*>(bias + col);
                float2 r0 = *reinterpret_cast<const float2*>(res + i0);
                float2 r1 = *reinterpret_cast<const float2*>(res + i1);
                c0 += bb.x + r0.x; c1 += bb.y + r0.y;
                c2 += bb.x + r1.x; c3 += bb.y + r1.y;
            } else if (EPI == 2) {
                float2 bb = *reinterpret_cast<const float2*>(bias + col);
                c0 = gelu_exact(c0 + bb.x); c1 = gelu_exact(c1 + bb.y);
                c2 = gelu_exact(c2 + bb.x); c3 = gelu_exact(c3 + bb.y);
            }
            *reinterpret_cast<float2*>(Cout + i0) = make_float2(c0, c1);
            *reinterpret_cast<float2*>(Cout + i1) = make_float2(c2, c3);
        }
    }
}

// ---------------------------------------------------------------------------
// Attention: one block per (b,h). N=15, HS=64. All in smem; fp32 math.
// logits(q,k) = sum_d Jq*Jk + Iq*Ik + Iv*Wc[d][k], scaled 0.125, softmax, @Jv
// ---------------------------------------------------------------------------
__global__ __launch_bounds__(256) void attn_kernel(
    const float* __restrict__ Jqkv, const float* __restrict__ Iqkv,
    const float* __restrict__ Wc, float* __restrict__ out) {
    int b = blockIdx.x, h = blockIdx.y;
    __shared__ float sm[6][15][64];  // Jq Jk Jv Iq Ik Iv
    __shared__ float swc[64][15];
    __shared__ float slog[15][16];
    int tid = threadIdx.x;
    size_t base = ((size_t)b * 15) * 3072 + h * 64;

    for (int idx = tid; idx < 1440; idx += 256) {
        int mat = idx / 240;
        int rem = idx % 240;
        int n = rem >> 4;
        int d4 = rem & 15;
        const float* src = (mat < 3) ? Jqkv : Iqkv;
        int qkv = (mat < 3) ? mat : mat - 3;
        float4 v = *reinterpret_cast<const float4*>(
            src + base + (size_t)n * 3072 + qkv * 1024 + d4 * 4);
        *reinterpret_cast<float4*>(&sm[mat][n][d4 * 4]) = v;
    }
    for (int idx = tid; idx < 960; idx += 256)
        reinterpret_cast<float*>(swc)[idx] = Wc[idx];
    __syncthreads();

    if (tid < 225) {
        int q = tid / 15, k = tid % 15;
        float s = 0.f;
#pragma unroll 8
        for (int d = 0; d < 64; d++) {
            s += sm[0][q][d] * sm[1][k][d];  // Jq.Jk
            s += sm[3][q][d] * sm[4][k][d];  // Iq.Ik
            s += sm[5][q][d] * swc[d][k];    // Iv @ Wc
        }
        slog[q][k] = s * 0.125f;
    }
    __syncthreads();
    if (tid < 15) {
        int q = tid;
        float mx = -1e30f;
#pragma unroll
        for (int k = 0; k < 15; k++) mx = fmaxf(mx, slog[q][k]);
        float sum = 0.f;
#pragma unroll
        for (int k = 0; k < 15; k++) {
            float e = expf(slog[q][k] - mx);
            slog[q][k] = e;
            sum += e;
        }
        float inv = 1.0f / sum;
#pragma unroll
        for (int k = 0; k < 15; k++) slog[q][k] *= inv;
    }
    __syncthreads();
    for (int idx = tid; idx < 960; idx += 256) {
        int q = idx >> 6, d = idx & 63;
        float s = 0.f;
#pragma unroll
        for (int k = 0; k < 15; k++) s += slog[q][k] * sm[2][k][d];
        out[((size_t)b * 15 + q) * 1024 + h * 64 + d] = s;
    }
}

// ---------------------------------------------------------------------------
extern "C" void kernel_launch(void* const* d_in, const int* in_sizes, int n_in,
                              void* d_out, int out_size) {
    const float* joint  = (const float*)d_in[0];
    const float* rel    = (const float*)d_in[1];
    const float* W_Jqkv = (const float*)d_in[2];
    const float* W_Iqk  = (const float*)d_in[3];
    const float* W_Iconv= (const float*)d_in[4];
    const float* W_proj = (const float*)d_in[5];
    const float* b_proj = (const float*)d_in[6];
    const float* g1 = (const float*)d_in[7];
    const float* b1 = (const float*)d_in[8];
    const float* g2 = (const float*)d_in[9];
    const float* b2 = (const float*)d_in[10];
    const float* gj = (const float*)d_in[11];
    const float* bj = (const float*)d_in[12];
    const float* W_fc1 = (const float*)d_in[13];
    const float* b_fc1 = (const float*)d_in[14];
    const float* W_fc2 = (const float*)d_in[15];
    const float* b_fc2 = (const float*)d_in[16];
    float* out = (float*)d_out;

    float *bufA, *bufB, *Jqkv, *Iqkv, *jointb, *hid;
    cudaGetSymbolAddress((void**)&bufA, g_bufA);
    cudaGetSymbolAddress((void**)&bufB, g_bufB);
    cudaGetSymbolAddress((void**)&Jqkv, g_Jqkv);
    cudaGetSymbolAddress((void**)&Iqkv, g_Iqkv);
    cudaGetSymbolAddress((void**)&jointb, g_joint);
    cudaGetSymbolAddress((void**)&hid, g_hid);

    // 1. dual LN
    ln_kernel<<<M_ROWS, 256>>>(joint, g1, b1, bufA);
    ln_kernel<<<M_ROWS, 256>>>(rel, g2, b2, bufB);
    // 2/3. QKV projections
    gemm_tf32<0><<<dim3(24, 240), 256>>>(bufA, W_Jqkv, nullptr, nullptr, Jqkv,
                                         M_ROWS, 3072, 1024);
    gemm_tf32<0><<<dim3(24, 240), 256>>>(bufB, W_Iqk, nullptr, nullptr, Iqkv,
                                         M_ROWS, 3072, 1024);
    // 4. attention (reuses bufB for output)
    attn_kernel<<<dim3(2048, 16), 256>>>(Jqkv, Iqkv, W_Iconv, bufB);
    // 5. proj + bias + residual(joint_feature)
    gemm_tf32<1><<<dim3(8, 240), 256>>>(bufB, W_proj, b_proj, joint, jointb,
                                        M_ROWS, 1024, 1024);
    // 6. MLP
    ln_kernel<<<M_ROWS, 256>>>(jointb, gj, bj, bufA);
    gemm_tf32<2><<<dim3(4, 240), 256>>>(bufA, W_fc1, b_fc1, nullptr, hid,
                                        M_ROWS, 512, 1024);
    gemm_tf32<1><<<dim3(8, 240), 256>>>(hid, W_fc2, b_fc2, jointb, out,
                                        M_ROWS, 1024, 512);
}

// round 2
// speedup vs baseline: 1.5668x; 1.5668x over previous
#include <cuda_runtime.h>
#include <cuda_bf16.h>
#include <math.h>

// ---------------------------------------------------------------------------
// Fused transformer block: B=2048, N=15, C=1024, H=16, HS=64
// Round 2: bf16 tensor-core GEMMs (m16n8k16) + ldmatrix + cp.async pipeline.
// ---------------------------------------------------------------------------

#define M_ROWS 30720
using bf16 = __nv_bfloat16;

// scratch (device globals: allocation-free per harness rules)
__device__ bf16  g_xj[(size_t)M_ROWS * 1024];
__device__ bf16  g_xi[(size_t)M_ROWS * 1024];
__device__ bf16  g_Jqkv[(size_t)M_ROWS * 3072];
__device__ bf16  g_Iqkv[(size_t)M_ROWS * 3072];
__device__ bf16  g_attno[(size_t)M_ROWS * 1024];
__device__ bf16  g_ln2[(size_t)M_ROWS * 1024];
__device__ bf16  g_hid[(size_t)M_ROWS * 512];
__device__ float g_joint[(size_t)M_ROWS * 1024];
// bf16 weights
__device__ bf16 g_wJ[1024 * 3072];
__device__ bf16 g_wI[1024 * 3072];
__device__ bf16 g_wP[1024 * 1024];
__device__ bf16 g_w1[1024 * 512];
__device__ bf16 g_w2[512 * 1024];

// ---------------------------------------------------------------------------
// fp32 -> bf16 conversion (weights), 4 elems/thread
// ---------------------------------------------------------------------------
__global__ __launch_bounds__(256) void f2bf_kernel(const float* __restrict__ in,
                                                   bf16* __restrict__ out, int n) {
    int i = (blockIdx.x * 256 + threadIdx.x) * 4;
    if (i < n) {
        float4 v = *reinterpret_cast<const float4*>(in + i);
        __nv_bfloat162 a = __floats2bfloat162_rn(v.x, v.y);
        __nv_bfloat162 b = __floats2bfloat162_rn(v.z, v.w);
        *reinterpret_cast<__nv_bfloat162*>(out + i) = a;
        *reinterpret_cast<__nv_bfloat162*>(out + i + 2) = b;
    }
}

// ---------------------------------------------------------------------------
// LayerNorm: one block per row of 1024, 256 threads, float4/thread, bf16 out
// ---------------------------------------------------------------------------
__global__ __launch_bounds__(256) void ln_kernel(
    const float* __restrict__ x, const float* __restrict__ g,
    const float* __restrict__ b, bf16* __restrict__ out) {
    int row = blockIdx.x;
    const float4* xr = reinterpret_cast<const float4*>(x + (size_t)row * 1024);
    float4 v = xr[threadIdx.x];
    float s = v.x + v.y + v.z + v.w;
    float sq = v.x * v.x + v.y * v.y + v.z * v.z + v.w * v.w;
#pragma unroll
    for (int o = 16; o > 0; o >>= 1) {
        s += __shfl_xor_sync(0xffffffffu, s, o);
        sq += __shfl_xor_sync(0xffffffffu, sq, o);
    }
    __shared__ float ss[8], ssq[8];
    int w = threadIdx.x >> 5;
    if ((threadIdx.x & 31) == 0) { ss[w] = s; ssq[w] = sq; }
    __syncthreads();
    float ts = 0.f, tq = 0.f;
#pragma unroll
    for (int i = 0; i < 8; i++) { ts += ss[i]; tq += ssq[i]; }
    float mean = ts * (1.0f / 1024.0f);
    float var = tq * (1.0f / 1024.0f) - mean * mean;
    float rstd = rsqrtf(var + 1e-5f);
    int c = threadIdx.x * 4;
    float4 gg = *reinterpret_cast<const float4*>(g + c);
    float4 bb = *reinterpret_cast<const float4*>(b + c);
    float o0 = (v.x - mean) * rstd * gg.x + bb.x;
    float o1 = (v.y - mean) * rstd * gg.y + bb.y;
    float o2 = (v.z - mean) * rstd * gg.z + bb.z;
    float o3 = (v.w - mean) * rstd * gg.w + bb.w;
    bf16* orow = out + (size_t)row * 1024 + c;
    *reinterpret_cast<__nv_bfloat162*>(orow) = __floats2bfloat162_rn(o0, o1);
    *reinterpret_cast<__nv_bfloat162*>(orow + 2) = __floats2bfloat162_rn(o2, o3);
}

// ---------------------------------------------------------------------------
// cp.async helpers
// ---------------------------------------------------------------------------
__device__ __forceinline__ void cp16(void* dst, const void* src) {
    unsigned d = (unsigned)__cvta_generic_to_shared(dst);
    asm volatile("cp.async.cg.shared.global [%0], [%1], 16;\n" ::"r"(d), "l"(src));
}
__device__ __forceinline__ void cp_commit() {
    asm volatile("cp.async.commit_group;\n");
}
template <int NN>
__device__ __forceinline__ void cp_wait() {
    asm volatile("cp.async.wait_group %0;\n" ::"n"(NN));
}

__device__ __forceinline__ float gelu_exact(float x) {
    return 0.5f * x * (1.0f + erff(x * 0.70710678118654752f));
}

// ---------------------------------------------------------------------------
// bf16 GEMM: C[M,N] = A[M,K] @ B[K,N] (+ epilogue)
// Block tile 128x128x32, 8 warps (64x32 warp tiles), m16n8k16 bf16 MMA.
// ldmatrix fragment loads, cp.async 2-stage pipeline.
// EPI: 0=plain (OT out), 1=+bias+residual(fp32), 2=+bias then exact GELU
// ---------------------------------------------------------------------------
template <int EPI, typename OT>
__global__ __launch_bounds__(256) void gemm_bf16(
    const bf16* __restrict__ A, const bf16* __restrict__ B,
    const float* __restrict__ bias, const float* __restrict__ res,
    OT* __restrict__ Cout, int M, int N, int K) {
    __shared__ bf16 As[2][128][40];   // 80B rows: LDSM phases conflict-free
    __shared__ bf16 Bs[2][32][136];   // 272B rows: conflict-free

    int tid = threadIdx.x;
    int bm = blockIdx.y * 128;
    int bn = blockIdx.x * 128;

    int lane = tid & 31, wid = tid >> 5;
    int wm = (wid >> 2) * 64;
    int wn = (wid & 3) * 32;
    int g = lane >> 2, tg = lane & 3;

    // loader mapping: 512 A-chunks (16B) + 512 B-chunks, 2+2 per thread
    int ar0 = tid >> 1;                 // A rows handled: tid/2 (chunk pair trick)
    // simpler: chunk ids {tid, tid+256}
    float acc[4][4][4];
#pragma unroll
    for (int a = 0; a < 4; a++)
#pragma unroll
        for (int b2 = 0; b2 < 4; b2++)
#pragma unroll
            for (int c = 0; c < 4; c++) acc[a][b2][c] = 0.f;
    (void)ar0;

    auto load_tile = [&](int st, int t) {
#pragma unroll
        for (int p = 0; p < 2; p++) {
            int c = tid + p * 256;
            int arow = c >> 2, ach = c & 3;
            cp16(&As[st][arow][ach * 8],
                 A + (size_t)(bm + arow) * K + t * 32 + ach * 8);
            int brow = c >> 4, bch = c & 15;
            cp16(&Bs[st][brow][bch * 8],
                 B + (size_t)(t * 32 + brow) * N + bn + bch * 8);
        }
    };

    load_tile(0, 0);
    cp_commit();

    int nk = K >> 5;
    for (int t = 0; t < nk; ++t) {
        if (t + 1 < nk) {
            load_tile((t + 1) & 1, t + 1);
            cp_commit();
            cp_wait<1>();
        } else {
            cp_wait<0>();
        }
        __syncthreads();
        int st = t & 1;
#pragma unroll
        for (int kk = 0; kk < 32; kk += 16) {
            unsigned af[4][4], bfr[2][4];
#pragma unroll
            for (int mt = 0; mt < 4; mt++) {
                unsigned addr = (unsigned)__cvta_generic_to_shared(
                    &As[st][wm + mt * 16 + (lane & 15)][kk + (lane >> 4) * 8]);
                asm volatile(
                    "ldmatrix.sync.aligned.m8n8.x4.shared.b16 {%0,%1,%2,%3},[%4];"
                    : "=r"(af[mt][0]), "=r"(af[mt][1]), "=r"(af[mt][2]),
                      "=r"(af[mt][3])
                    : "r"(addr));
            }
#pragma unroll
            for (int hh = 0; hh < 2; hh++) {
                unsigned addr = (unsigned)__cvta_generic_to_shared(
                    &Bs[st][kk + (lane & 15)][wn + hh * 16 + (lane >> 4) * 8]);
                asm volatile(
                    "ldmatrix.sync.aligned.m8n8.x4.trans.shared.b16 "
                    "{%0,%1,%2,%3},[%4];"
                    : "=r"(bfr[hh][0]), "=r"(bfr[hh][1]), "=r"(bfr[hh][2]),
                      "=r"(bfr[hh][3])
                    : "r"(addr));
            }
#pragma unroll
            for (int mt = 0; mt < 4; mt++)
#pragma unroll
                for (int nt = 0; nt < 4; nt++) {
                    unsigned b0 = bfr[nt >> 1][(nt & 1) * 2];
                    unsigned b1 = bfr[nt >> 1][(nt & 1) * 2 + 1];
                    asm volatile(
                        "mma.sync.aligned.m16n8k16.row.col.f32.bf16.bf16.f32 "
                        "{%0,%1,%2,%3},{%4,%5,%6,%7},{%8,%9},{%0,%1,%2,%3};"
                        : "+f"(acc[mt][nt][0]), "+f"(acc[mt][nt][1]),
                          "+f"(acc[mt][nt][2]), "+f"(acc[mt][nt][3])
                        : "r"(af[mt][0]), "r"(af[mt][1]), "r"(af[mt][2]),
                          "r"(af[mt][3]), "r"(b0), "r"(b1));
                }
        }
        __syncthreads();
    }

    // epilogue
#pragma unroll
    for (int mt = 0; mt < 4; mt++) {
        int row = bm + wm + mt * 16 + g;
#pragma unroll
        for (int nt = 0; nt < 4; nt++) {
            int col = bn + wn + nt * 8 + 2 * tg;
            size_t i0 = (size_t)row * N + col;
            size_t i1 = i0 + (size_t)8 * N;
            float c0 = acc[mt][nt][0], c1 = acc[mt][nt][1];
            float c2 = acc[mt][nt][2], c3 = acc[mt][nt][3];
            if (EPI == 1) {
                float2 bb = *reinterpret_cast<const float2*>(bias + col);
                float2 r0 = *reinterpret_cast<const float2*>(res + i0);
                float2 r1 = *reinterpret_cast<const float2*>(res + i1);
                c0 += bb.x + r0.x; c1 += bb.y + r0.y;
                c2 += bb.x + r1.x; c3 += bb.y + r1.y;
            } else if (EPI == 2) {
                float2 bb = *reinterpret_cast<const float2*>(bias + col);
                c0 = gelu_exact(c0 + bb.x); c1 = gelu_exact(c1 + bb.y);
                c2 = gelu_exact(c2 + bb.x); c3 = gelu_exact(c3 + bb.y);
            }
            if (sizeof(OT) == 4) {
                *reinterpret_cast<float2*>((float*)Cout + i0) = make_float2(c0, c1);
                *reinterpret_cast<float2*>((float*)Cout + i1) = make_float2(c2, c3);
            } else {
                *reinterpret_cast<__nv_bfloat162*>((bf16*)Cout + i0) =
                    __floats2bfloat162_rn(c0, c1);
                *reinterpret_cast<__nv_bfloat162*>((bf16*)Cout + i1) =
                    __floats2bfloat162_rn(c2, c3);
            }
        }
    }
}

// ---------------------------------------------------------------------------
// Attention: one block per (b,h). N=15, HS=64. bf16 in/out, fp32 math in smem.
// ---------------------------------------------------------------------------
__global__ __launch_bounds__(256) void attn_kernel(
    const bf16* __restrict__ Jqkv, const bf16* __restrict__ Iqkv,
    const float* __restrict__ Wc, bf16* __restrict__ out) {
    int b = blockIdx.x, h = blockIdx.y;
    __shared__ float sm[6][15][64];  // Jq Jk Jv Iq Ik Iv
    __shared__ float swc[64][15];
    __shared__ float slog[15][16];
    int tid = threadIdx.x;
    size_t base = ((size_t)b * 15) * 3072 + h * 64;

    for (int idx = tid; idx < 720; idx += 256) {
        int mat = idx / 120;
        int rem = idx % 120;
        int n = rem >> 3;
        int c8 = rem & 7;
        const bf16* src = (mat < 3) ? Jqkv : Iqkv;
        int qkv = (mat < 3) ? mat : mat - 3;
        const __nv_bfloat162* p = reinterpret_cast<const __nv_bfloat162*>(
            src + base + (size_t)n * 3072 + qkv * 1024 + c8 * 8);
        float* d = &sm[mat][n][c8 * 8];
#pragma unroll
        for (int j = 0; j < 4; j++) {
            float2 f = __bfloat1622float2(p[j]);
            d[2 * j] = f.x;
            d[2 * j + 1] = f.y;
        }
    }
    for (int idx = tid; idx < 960; idx += 256)
        reinterpret_cast<float*>(swc)[idx] = Wc[idx];
    __syncthreads();

    if (tid < 225) {
        int q = tid / 15, k = tid % 15;
        float s = 0.f;
#pragma unroll 8
        for (int d = 0; d < 64; d++) {
            s += sm[0][q][d] * sm[1][k][d];  // Jq.Jk
            s += sm[3][q][d] * sm[4][k][d];  // Iq.Ik
            s += sm[5][q][d] * swc[d][k];    // Iv @ Wc
        }
        slog[q][k] = s * 0.125f;
    }
    __syncthreads();
    if (tid < 15) {
        int q = tid;
        float mx = -1e30f;
#pragma unroll
        for (int k = 0; k < 15; k++) mx = fmaxf(mx, slog[q][k]);
        float sum = 0.f;
#pragma unroll
        for (int k = 0; k < 15; k++) {
            float e = expf(slog[q][k] - mx);
            slog[q][k] = e;
            sum += e;
        }
        float inv = 1.0f / sum;
#pragma unroll
        for (int k = 0; k < 15; k++) slog[q][k] *= inv;
    }
    __syncthreads();
    for (int idx = tid; idx < 960; idx += 256) {
        int q = idx >> 6, d = idx & 63;
        float s = 0.f;
#pragma unroll
        for (int k = 0; k < 15; k++) s += slog[q][k] * sm[2][k][d];
        out[((size_t)b * 15 + q) * 1024 + h * 64 + d] = __float2bfloat16(s);
    }
}

// ---------------------------------------------------------------------------
extern "C" void kernel_launch(void* const* d_in, const int* in_sizes, int n_in,
                              void* d_out, int out_size) {
    const float* joint  = (const float*)d_in[0];
    const float* rel    = (const float*)d_in[1];
    const float* W_Jqkv = (const float*)d_in[2];
    const float* W_Iqk  = (const float*)d_in[3];
    const float* W_Iconv= (const float*)d_in[4];
    const float* W_proj = (const float*)d_in[5];
    const float* b_proj = (const float*)d_in[6];
    const float* g1 = (const float*)d_in[7];
    const float* b1 = (const float*)d_in[8];
    const float* g2 = (const float*)d_in[9];
    const float* b2 = (const float*)d_in[10];
    const float* gj = (const float*)d_in[11];
    const float* bj = (const float*)d_in[12];
    const float* W_fc1 = (const float*)d_in[13];
    const float* b_fc1 = (const float*)d_in[14];
    const float* W_fc2 = (const float*)d_in[15];
    const float* b_fc2 = (const float*)d_in[16];
    float* out = (float*)d_out;

    bf16 *xj, *xi, *Jqkv, *Iqkv, *attno, *ln2, *hid;
    bf16 *wJ, *wI, *wP, *w1, *w2;
    float* jointb;
    cudaGetSymbolAddress((void**)&xj, g_xj);
    cudaGetSymbolAddress((void**)&xi, g_xi);
    cudaGetSymbolAddress((void**)&Jqkv, g_Jqkv);
    cudaGetSymbolAddress((void**)&Iqkv, g_Iqkv);
    cudaGetSymbolAddress((void**)&attno, g_attno);
    cudaGetSymbolAddress((void**)&ln2, g_ln2);
    cudaGetSymbolAddress((void**)&hid, g_hid);
    cudaGetSymbolAddress((void**)&jointb, g_joint);
    cudaGetSymbolAddress((void**)&wJ, g_wJ);
    cudaGetSymbolAddress((void**)&wI, g_wI);
    cudaGetSymbolAddress((void**)&wP, g_wP);
    cudaGetSymbolAddress((void**)&w1, g_w1);
    cudaGetSymbolAddress((void**)&w2, g_w2);

    // weight conversion fp32 -> bf16
    f2bf_kernel<<<3072, 256>>>(W_Jqkv, wJ, 1024 * 3072);
    f2bf_kernel<<<3072, 256>>>(W_Iqk, wI, 1024 * 3072);
    f2bf_kernel<<<1024, 256>>>(W_proj, wP, 1024 * 1024);
    f2bf_kernel<<<512, 256>>>(W_fc1, w1, 1024 * 512);
    f2bf_kernel<<<512, 256>>>(W_fc2, w2, 512 * 1024);

    // 1. dual LN (fp32 in, bf16 out)
    ln_kernel<<<M_ROWS, 256>>>(joint, g1, b1, xj);
    ln_kernel<<<M_ROWS, 256>>>(rel, g2, b2, xi);
    // 2/3. QKV projections (bf16 out)
    gemm_bf16<0, bf16><<<dim3(24, 240), 256>>>(xj, wJ, nullptr, nullptr, Jqkv,
                                               M_ROWS, 3072, 1024);
    gemm_bf16<0, bf16><<<dim3(24, 240), 256>>>(xi, wI, nullptr, nullptr, Iqkv,
                                               M_ROWS, 3072, 1024);
    // 4. attention
    attn_kernel<<<dim3(2048, 16), 256>>>(Jqkv, Iqkv, W_Iconv, attno);
    // 5. proj + bias + residual(joint_feature)  -> fp32 joint
    gemm_bf16<1, float><<<dim3(8, 240), 256>>>(attno, wP, b_proj, joint, jointb,
                                               M_ROWS, 1024, 1024);
    // 6. MLP
    ln_kernel<<<M_ROWS, 256>>>(jointb, gj, bj, ln2);
    gemm_bf16<2, bf16><<<dim3(4, 240), 256>>>(ln2, w1, b_fc1, nullptr, hid,
                                              M_ROWS, 512, 1024);
    gemm_bf16<1, float><<<dim3(8, 240), 256>>>(hid, w2, b_fc2, jointb, out,
                                               M_ROWS, 1024, 512);
}